// round 15
// baseline (speedup 1.0000x reference)
#include <cuda_runtime.h>
#include <cuda_fp16.h>
#include <cstdint>

// Problem shape (fixed)
#define S_TOK 2048
#define K_DIM 4096
#define O_DIM 4096
#define NGRP  32

// GEMM tiling
#define BM 128
#define BN 128
#define BK 64
#define NKT (K_DIM / BK)     // 64
#define THREADS 128          // 4 warps: 2 (M) x 2 (N), warp tile 64x64
#define NSTAGE 3

// Device-global scratch (no runtime allocation allowed)
__device__ __align__(128) __half g_xq[(size_t)S_TOK * K_DIM];   // centered quantized activations
__device__ float  g_xscale[S_TOK];
__device__ __align__(128) __half g_wq[(size_t)O_DIM * K_DIM];   // dequantized weights (code-zp)*scale

// ---------------------------------------------------------------------------
// Kernel 1 (fused prep): blocks [0,2048) = activation quant, [2048,6144) = weight dequant
// ---------------------------------------------------------------------------
__global__ __launch_bounds__(256) void prep_kernel(
    const float* __restrict__ x,
    const int* __restrict__ qw, const float* __restrict__ wsc, const int* __restrict__ wzp)
{
    const int tid = threadIdx.x;

    if (blockIdx.x < S_TOK) {
        // ---- activation quantization ----
        const int row = blockIdx.x;
        const float* xr = x + (size_t)row * K_DIM;

        float4 v[4];
        float mn = INFINITY, mx = -INFINITY;
#pragma unroll
        for (int i = 0; i < 4; i++) {
            v[i] = __ldcs(((const float4*)xr) + tid + i * 256);   // streaming read-once
            mn = fminf(mn, fminf(fminf(v[i].x, v[i].y), fminf(v[i].z, v[i].w)));
            mx = fmaxf(mx, fmaxf(fmaxf(v[i].x, v[i].y), fmaxf(v[i].z, v[i].w)));
        }
#pragma unroll
        for (int o = 16; o; o >>= 1) {
            mn = fminf(mn, __shfl_xor_sync(0xffffffffu, mn, o));
            mx = fmaxf(mx, __shfl_xor_sync(0xffffffffu, mx, o));
        }
        __shared__ float smn[8], smx[8];
        __shared__ float s_inv, s_zp;
        const int wid = tid >> 5, lane = tid & 31;
        if (lane == 0) { smn[wid] = mn; smx[wid] = mx; }
        __syncthreads();
        if (tid == 0) {
            float a = smn[0], b = smx[0];
#pragma unroll
            for (int i = 1; i < 8; i++) { a = fminf(a, smn[i]); b = fmaxf(b, smx[i]); }
            float sc = fmaxf((b - a) * (1.0f / 255.0f), 1e-5f);
            float zp = fminf(fmaxf(rintf(-a / sc), 0.0f), 255.0f);
            s_inv = 1.0f / sc; s_zp = zp;
            g_xscale[row] = sc;
        }
        __syncthreads();
        const float inv = s_inv, zp = s_zp;

        __half* outp = g_xq + (size_t)row * K_DIM;
#pragma unroll
        for (int i = 0; i < 4; i++) {
            float q0 = fminf(fmaxf(rintf(v[i].x * inv) + zp, 0.0f), 255.0f) - zp;
            float q1 = fminf(fmaxf(rintf(v[i].y * inv) + zp, 0.0f), 255.0f) - zp;
            float q2 = fminf(fmaxf(rintf(v[i].z * inv) + zp, 0.0f), 255.0f) - zp;
            float q3 = fminf(fmaxf(rintf(v[i].w * inv) + zp, 0.0f), 255.0f) - zp;
            __half2 p0, p1;
            p0.x = __float2half_rn(q0); p0.y = __float2half_rn(q1);
            p1.x = __float2half_rn(q2); p1.y = __float2half_rn(q3);
            ((__half2*)outp)[(tid + i * 256) * 2 + 0] = p0;
            ((__half2*)outp)[(tid + i * 256) * 2 + 1] = p1;
        }
    } else {
        // ---- weight dequant ----
        const int o = blockIdx.x - S_TOK;
        const int g = tid >> 3;
        const float s = wsc[o * NGRP + g];
        const float z = (float)wzp[o * NGRP + g];
        const int4* src = (const int4*)(qw + (size_t)o * K_DIM + tid * 16);
        __half2 h[8];
#pragma unroll
        for (int j = 0; j < 4; j++) {
            int4 c = __ldcs(src + j);                             // streaming read-once
            h[j * 2 + 0].x = __float2half_rn(((float)c.x - z) * s);
            h[j * 2 + 0].y = __float2half_rn(((float)c.y - z) * s);
            h[j * 2 + 1].x = __float2half_rn(((float)c.z - z) * s);
            h[j * 2 + 1].y = __float2half_rn(((float)c.w - z) * s);
        }
        uint4* dst = (uint4*)(g_wq + (size_t)o * K_DIM + tid * 16);
        dst[0] = *(uint4*)&h[0];
        dst[1] = *(uint4*)&h[4];
    }
}

// ---------------------------------------------------------------------------
// Kernel 2: fp16 GEMM (R13 config) with INTERLEAVED stage loads: the 16
//           cp.async per thread per k-iter are issued in 4 quarters, each
//           AFTER an mma_block, so LDGSTS issue overlaps tensor drain
//           instead of delaying the first LDSM after the barrier.
// ---------------------------------------------------------------------------
#define MMA16816(d, a0, a1, a2, a3, b0, b1)                                        \
    asm volatile(                                                                  \
        "mma.sync.aligned.m16n8k16.row.col.f32.f16.f16.f32 "                       \
        "{%0,%1,%2,%3},{%4,%5,%6,%7},{%8,%9},{%0,%1,%2,%3};"                       \
        : "+f"(d[0]), "+f"(d[1]), "+f"(d[2]), "+f"(d[3])                           \
        : "r"(a0), "r"(a1), "r"(a2), "r"(a3), "r"(b0), "r"(b1))

#define LDSM_X4(r0, r1, r2, r3, addr)                                              \
    asm volatile("ldmatrix.sync.aligned.m8n8.x4.shared.b16 {%0,%1,%2,%3},[%4];"    \
                 : "=r"(r0), "=r"(r1), "=r"(r2), "=r"(r3) : "r"(addr))

__device__ __forceinline__ void cp_async16(uint32_t saddr, const void* g) {
    asm volatile("cp.async.cg.shared.global [%0], [%1], 16;" :: "r"(saddr), "l"(g));
}
#define CP_COMMIT() asm volatile("cp.async.commit_group;")
#define CP_WAIT0()  asm volatile("cp.async.wait_group 0;")
#define CP_WAIT1()  asm volatile("cp.async.wait_group 1;")

// rows of 64 fp16 = 128B; 16B chunk c swizzled by row
__device__ __forceinline__ uint32_t sw(int r, int c) {
    return (uint32_t)(r * 128 + ((c ^ (r & 7)) << 4));
}

#define A_BYTES (BM * 128)                   // 16384
#define B_BYTES (BN * 128)                   // 16384
#define STAGE_BYTES (A_BYTES + B_BYTES)      // 32768
#define GEMM_SMEM (NSTAGE * STAGE_BYTES)     // 98304 -> 2 CTAs/SM

extern __shared__ char smem_raw[];

__global__ __launch_bounds__(THREADS, 2) void gemm_f16_kernel(
    const float* __restrict__ bias, float* __restrict__ out)
{
    const int tid  = threadIdx.x;
    const int warp = tid >> 5, lane = tid & 31;
    const int warp_m = warp & 1;   // 2 along M (64 rows)
    const int warp_n = warp >> 1;  // 2 along N (64 cols)
    const int bm = (blockIdx.x & 15) * BM;   // m fastest -> weight L2 reuse
    const int bn = (blockIdx.x >> 4) * BN;

    const uint32_t sbase = (uint32_t)__cvta_generic_to_shared(smem_raw);

    const __half* gA = g_xq + (size_t)bm * K_DIM;
    const __half* gB = g_wq + (size_t)bn * K_DIM;

    // full stage load (prologue only)
    auto load_stage = [&](int s, int kt) {
        const uint32_t a_s = sbase + s * STAGE_BYTES;
        const uint32_t b_s = a_s + A_BYTES;
        const size_t koff = (size_t)kt * BK;
#pragma unroll
        for (int i = 0; i < 8; i++) {
            const int ch = tid + i * 128;
            const int r = ch >> 3, c = ch & 7;
            cp_async16(a_s + sw(r, c), gA + (size_t)r * K_DIM + koff + c * 8);
        }
#pragma unroll
        for (int i = 0; i < 8; i++) {
            const int ch = tid + i * 128;
            const int r = ch >> 3, c = ch & 7;
            cp_async16(b_s + sw(r, c), gB + (size_t)r * K_DIM + koff + c * 8);
        }
        CP_COMMIT();
    };

    // quarter stage load: A chunks 2q,2q+1 and B chunks 2q,2q+1 (4 cp.async)
    auto load_quarter = [&](int s, int kt, int q) {
        const uint32_t a_s = sbase + s * STAGE_BYTES;
        const uint32_t b_s = a_s + A_BYTES;
        const size_t koff = (size_t)kt * BK;
#pragma unroll
        for (int i = 2 * q; i < 2 * q + 2; i++) {
            const int ch = tid + i * 128;
            const int r = ch >> 3, c = ch & 7;
            cp_async16(a_s + sw(r, c), gA + (size_t)r * K_DIM + koff + c * 8);
        }
#pragma unroll
        for (int i = 2 * q; i < 2 * q + 2; i++) {
            const int ch = tid + i * 128;
            const int r = ch >> 3, c = ch & 7;
            cp_async16(b_s + sw(r, c), gB + (size_t)r * K_DIM + koff + c * 8);
        }
    };

    float acc[4][8][4];
#pragma unroll
    for (int i = 0; i < 4; i++)
#pragma unroll
        for (int j = 0; j < 8; j++)
#pragma unroll
            for (int k = 0; k < 4; k++) acc[i][j][k] = 0.f;

    // lane-constant fragment addressing
    const int arow = warp_m * 64 + (lane & 15);                   // + mi*16
    const int brow = warp_n * 64 + (lane >> 4) * 8 + (lane & 7);  // + nj*16
    const int ac_lo = (lane >> 4);                                // + ks*2
    const int bc_lo = ((lane >> 3) & 1);                          // + ks*2

    uint32_t af[2][4][4], bf[4][4];

    auto ldsm_a = [&](int buf, uint32_t a_s, int ks) {
#pragma unroll
        for (int mi = 0; mi < 4; mi++)
            LDSM_X4(af[buf][mi][0], af[buf][mi][1], af[buf][mi][2], af[buf][mi][3],
                    a_s + sw(arow + mi * 16, ks * 2 + ac_lo));
    };
    auto ldsm_b = [&](uint32_t b_s, int ks) {
#pragma unroll
        for (int nj = 0; nj < 4; nj++)
            LDSM_X4(bf[nj][0], bf[nj][1], bf[nj][2], bf[nj][3],
                    b_s + sw(brow + nj * 16, ks * 2 + bc_lo));
    };
    auto mma_block = [&](int buf) {
#pragma unroll
        for (int mi = 0; mi < 4; mi++)
#pragma unroll
            for (int nj = 0; nj < 4; nj++) {
                MMA16816(acc[mi][nj * 2 + 0],
                         af[buf][mi][0], af[buf][mi][1], af[buf][mi][2], af[buf][mi][3],
                         bf[nj][0], bf[nj][1]);
                MMA16816(acc[mi][nj * 2 + 1],
                         af[buf][mi][0], af[buf][mi][1], af[buf][mi][2], af[buf][mi][3],
                         bf[nj][2], bf[nj][3]);
            }
    };

    // prologue: stages 0 and 1 in flight; preload A fragments for (kt=0, ks=0)
    load_stage(0, 0);
    load_stage(1, 1);
    CP_WAIT1();                 // own-warp stage-0 loads retired
    __syncthreads();            // all warps' stage-0 loads retired
    ldsm_a(0, sbase, 0);

    for (int kt = 0; kt < NKT; kt++) {
        const int s = kt % NSTAGE;

        CP_WAIT0();             // stages <= kt+1 retired (own warp)
        __syncthreads();        // ... across all warps; prev-stage reads done

        const uint32_t a_s = sbase + s * STAGE_BYTES;
        const uint32_t b_s = a_s + A_BYTES;
        const uint32_t a_next = sbase + ((kt + 1) % NSTAGE) * STAGE_BYTES;
        const bool do_load = (kt + 2 < NKT);
        const int s_ld = (kt + 2) % NSTAGE;

        // flattened steps: fragments for ks+1 (or next kt's ks0) ahead of
        // MMAs of ks; the kt+2 stage load is issued in quarters AFTER each
        // mma_block so LDGSTS issue hides behind tensor-pipe drain.
#pragma unroll
        for (int ks = 0; ks < 4; ks++) {
            ldsm_b(b_s, ks);
            if (ks < 3) ldsm_a((ks + 1) & 1, a_s, ks + 1);
            else        ldsm_a(0, a_next, 0);   // cross-boundary prefetch (safe: see wait0)
            mma_block(ks & 1);
            if (do_load) load_quarter(s_ld, kt + 2, ks);
        }
        if (do_load) CP_COMMIT();               // one group per kt, as before
    }

    // epilogue: out = acc * x_scale[row] + bias[col]  (streaming stores)
#pragma unroll
    for (int mi = 0; mi < 4; mi++) {
        const int row0 = bm + warp_m * 64 + mi * 16 + (lane >> 2);
        const int row1 = row0 + 8;
        const float xs0 = g_xscale[row0];
        const float xs1 = g_xscale[row1];
        float* p0 = out + (size_t)row0 * O_DIM + bn;
        float* p1 = out + (size_t)row1 * O_DIM + bn;
#pragma unroll
        for (int nj = 0; nj < 8; nj++) {
            const int col = warp_n * 64 + nj * 8 + (lane & 3) * 2;
            const float2 bv = *(const float2*)(bias + bn + col);
            float2 o0, o1;
            o0.x = acc[mi][nj][0] * xs0 + bv.x;
            o0.y = acc[mi][nj][1] * xs0 + bv.y;
            o1.x = acc[mi][nj][2] * xs1 + bv.x;
            o1.y = acc[mi][nj][3] * xs1 + bv.y;
            __stcs((float2*)(p0 + col), o0);
            __stcs((float2*)(p1 + col), o1);
        }
    }
}

// ---------------------------------------------------------------------------
extern "C" void kernel_launch(void* const* d_in, const int* in_sizes, int n_in,
                              void* d_out, int out_size) {
    const float* x        = (const float*)d_in[0];
    const int*   qweight  = (const int*)d_in[1];
    const float* w_scales = (const float*)d_in[2];
    const int*   w_zp     = (const int*)d_in[3];
    const float* bias     = (const float*)d_in[4];
    float*       out      = (float*)d_out;

    prep_kernel<<<S_TOK + O_DIM, 256>>>(x, qweight, w_scales, w_zp);

    cudaFuncSetAttribute(gemm_f16_kernel,
                         cudaFuncAttributeMaxDynamicSharedMemorySize, GEMM_SMEM);
    const int grid = (S_TOK / BM) * (O_DIM / BN);   // 16 x 32 = 512
    gemm_f16_kernel<<<grid, THREADS, GEMM_SMEM>>>(bias, out);
}

// round 16
// speedup vs baseline: 1.1763x; 1.1763x over previous
#include <cuda_runtime.h>
#include <cuda_fp16.h>
#include <cstdint>

// Problem shape (fixed)
#define S_TOK 2048
#define K_DIM 4096
#define O_DIM 4096
#define NGRP  32

// GEMM tiling
#define BM 128
#define BN 128
#define BK 64
#define NKT (K_DIM / BK)     // 64
#define THREADS 128          // 4 warps: 2 (M) x 2 (N), warp tile 64x64
#define NSTAGE 3

// Device-global scratch (no runtime allocation allowed)
__device__ __align__(128) __half g_xq[(size_t)S_TOK * K_DIM];   // centered quantized activations
__device__ float  g_xscale[S_TOK];
__device__ __align__(128) __half g_wq[(size_t)O_DIM * K_DIM];   // dequantized weights (code-zp)*scale

// ---------------------------------------------------------------------------
// Kernel 1 (fused prep): blocks [0,2048) = activation quant, [2048,6144) = weight dequant
// ---------------------------------------------------------------------------
__global__ __launch_bounds__(256) void prep_kernel(
    const float* __restrict__ x,
    const int* __restrict__ qw, const float* __restrict__ wsc, const int* __restrict__ wzp)
{
    const int tid = threadIdx.x;

    if (blockIdx.x < S_TOK) {
        // ---- activation quantization ----
        const int row = blockIdx.x;
        const float* xr = x + (size_t)row * K_DIM;

        float4 v[4];
        float mn = INFINITY, mx = -INFINITY;
#pragma unroll
        for (int i = 0; i < 4; i++) {
            v[i] = __ldcs(((const float4*)xr) + tid + i * 256);   // streaming read-once
            mn = fminf(mn, fminf(fminf(v[i].x, v[i].y), fminf(v[i].z, v[i].w)));
            mx = fmaxf(mx, fmaxf(fmaxf(v[i].x, v[i].y), fmaxf(v[i].z, v[i].w)));
        }
#pragma unroll
        for (int o = 16; o; o >>= 1) {
            mn = fminf(mn, __shfl_xor_sync(0xffffffffu, mn, o));
            mx = fmaxf(mx, __shfl_xor_sync(0xffffffffu, mx, o));
        }
        __shared__ float smn[8], smx[8];
        __shared__ float s_inv, s_zp;
        const int wid = tid >> 5, lane = tid & 31;
        if (lane == 0) { smn[wid] = mn; smx[wid] = mx; }
        __syncthreads();
        if (tid == 0) {
            float a = smn[0], b = smx[0];
#pragma unroll
            for (int i = 1; i < 8; i++) { a = fminf(a, smn[i]); b = fmaxf(b, smx[i]); }
            float sc = fmaxf((b - a) * (1.0f / 255.0f), 1e-5f);
            float zp = fminf(fmaxf(rintf(-a / sc), 0.0f), 255.0f);
            s_inv = 1.0f / sc; s_zp = zp;
            g_xscale[row] = sc;
        }
        __syncthreads();
        const float inv = s_inv, zp = s_zp;

        __half* outp = g_xq + (size_t)row * K_DIM;
#pragma unroll
        for (int i = 0; i < 4; i++) {
            float q0 = fminf(fmaxf(rintf(v[i].x * inv) + zp, 0.0f), 255.0f) - zp;
            float q1 = fminf(fmaxf(rintf(v[i].y * inv) + zp, 0.0f), 255.0f) - zp;
            float q2 = fminf(fmaxf(rintf(v[i].z * inv) + zp, 0.0f), 255.0f) - zp;
            float q3 = fminf(fmaxf(rintf(v[i].w * inv) + zp, 0.0f), 255.0f) - zp;
            __half2 p0, p1;
            p0.x = __float2half_rn(q0); p0.y = __float2half_rn(q1);
            p1.x = __float2half_rn(q2); p1.y = __float2half_rn(q3);
            ((__half2*)outp)[(tid + i * 256) * 2 + 0] = p0;
            ((__half2*)outp)[(tid + i * 256) * 2 + 1] = p1;
        }
    } else {
        // ---- weight dequant ----
        const int o = blockIdx.x - S_TOK;
        const int g = tid >> 3;
        const float s = wsc[o * NGRP + g];
        const float z = (float)wzp[o * NGRP + g];
        const int4* src = (const int4*)(qw + (size_t)o * K_DIM + tid * 16);
        __half2 h[8];
#pragma unroll
        for (int j = 0; j < 4; j++) {
            int4 c = __ldcs(src + j);                             // streaming read-once
            h[j * 2 + 0].x = __float2half_rn(((float)c.x - z) * s);
            h[j * 2 + 0].y = __float2half_rn(((float)c.y - z) * s);
            h[j * 2 + 1].x = __float2half_rn(((float)c.z - z) * s);
            h[j * 2 + 1].y = __float2half_rn(((float)c.w - z) * s);
        }
        uint4* dst = (uint4*)(g_wq + (size_t)o * K_DIM + tid * 16);
        dst[0] = *(uint4*)&h[0];
        dst[1] = *(uint4*)&h[4];
    }
}

// ---------------------------------------------------------------------------
// Kernel 2: fp16 GEMM (R13 config, 236 regs). Single change vs R13: the
//           per-kt load_stage burst is issued AFTER the first fragment
//           LDSMs and BEFORE the first mma_block, so the LDGSTS issue
//           burst covers LDSM latency instead of delaying it.
// ---------------------------------------------------------------------------
#define MMA16816(d, a0, a1, a2, a3, b0, b1)                                        \
    asm volatile(                                                                  \
        "mma.sync.aligned.m16n8k16.row.col.f32.f16.f16.f32 "                       \
        "{%0,%1,%2,%3},{%4,%5,%6,%7},{%8,%9},{%0,%1,%2,%3};"                       \
        : "+f"(d[0]), "+f"(d[1]), "+f"(d[2]), "+f"(d[3])                           \
        : "r"(a0), "r"(a1), "r"(a2), "r"(a3), "r"(b0), "r"(b1))

#define LDSM_X4(r0, r1, r2, r3, addr)                                              \
    asm volatile("ldmatrix.sync.aligned.m8n8.x4.shared.b16 {%0,%1,%2,%3},[%4];"    \
                 : "=r"(r0), "=r"(r1), "=r"(r2), "=r"(r3) : "r"(addr))

__device__ __forceinline__ void cp_async16(uint32_t saddr, const void* g) {
    asm volatile("cp.async.cg.shared.global [%0], [%1], 16;" :: "r"(saddr), "l"(g));
}
#define CP_COMMIT() asm volatile("cp.async.commit_group;")
#define CP_WAIT0()  asm volatile("cp.async.wait_group 0;")
#define CP_WAIT1()  asm volatile("cp.async.wait_group 1;")

// rows of 64 fp16 = 128B; 16B chunk c swizzled by row
__device__ __forceinline__ uint32_t sw(int r, int c) {
    return (uint32_t)(r * 128 + ((c ^ (r & 7)) << 4));
}

#define A_BYTES (BM * 128)                   // 16384
#define B_BYTES (BN * 128)                   // 16384
#define STAGE_BYTES (A_BYTES + B_BYTES)      // 32768
#define GEMM_SMEM (NSTAGE * STAGE_BYTES)     // 98304 -> 2 CTAs/SM

extern __shared__ char smem_raw[];

__global__ __launch_bounds__(THREADS, 2) void gemm_f16_kernel(
    const float* __restrict__ bias, float* __restrict__ out)
{
    const int tid  = threadIdx.x;
    const int warp = tid >> 5, lane = tid & 31;
    const int warp_m = warp & 1;   // 2 along M (64 rows)
    const int warp_n = warp >> 1;  // 2 along N (64 cols)
    const int bm = (blockIdx.x & 15) * BM;   // m fastest -> weight L2 reuse
    const int bn = (blockIdx.x >> 4) * BN;

    const uint32_t sbase = (uint32_t)__cvta_generic_to_shared(smem_raw);

    const __half* gA = g_xq + (size_t)bm * K_DIM;
    const __half* gB = g_wq + (size_t)bn * K_DIM;

    auto load_stage = [&](int s, int kt) {
        const uint32_t a_s = sbase + s * STAGE_BYTES;
        const uint32_t b_s = a_s + A_BYTES;
        const size_t koff = (size_t)kt * BK;
#pragma unroll
        for (int i = 0; i < 8; i++) {           // A: 1024 chunks of 16B
            const int ch = tid + i * 128;
            const int r = ch >> 3, c = ch & 7;
            cp_async16(a_s + sw(r, c), gA + (size_t)r * K_DIM + koff + c * 8);
        }
#pragma unroll
        for (int i = 0; i < 8; i++) {           // B: 1024 chunks of 16B
            const int ch = tid + i * 128;
            const int r = ch >> 3, c = ch & 7;
            cp_async16(b_s + sw(r, c), gB + (size_t)r * K_DIM + koff + c * 8);
        }
        CP_COMMIT();
    };

    float acc[4][8][4];
#pragma unroll
    for (int i = 0; i < 4; i++)
#pragma unroll
        for (int j = 0; j < 8; j++)
#pragma unroll
            for (int k = 0; k < 4; k++) acc[i][j][k] = 0.f;

    // lane-constant fragment addressing
    const int arow = warp_m * 64 + (lane & 15);                   // + mi*16
    const int brow = warp_n * 64 + (lane >> 4) * 8 + (lane & 7);  // + nj*16
    const int ac_lo = (lane >> 4);                                // + ks*2
    const int bc_lo = ((lane >> 3) & 1);                          // + ks*2

    uint32_t af[2][4][4], bf[4][4];

    auto ldsm_a = [&](int buf, uint32_t a_s, int ks) {
#pragma unroll
        for (int mi = 0; mi < 4; mi++)
            LDSM_X4(af[buf][mi][0], af[buf][mi][1], af[buf][mi][2], af[buf][mi][3],
                    a_s + sw(arow + mi * 16, ks * 2 + ac_lo));
    };
    auto ldsm_b = [&](uint32_t b_s, int ks) {
#pragma unroll
        for (int nj = 0; nj < 4; nj++)
            LDSM_X4(bf[nj][0], bf[nj][1], bf[nj][2], bf[nj][3],
                    b_s + sw(brow + nj * 16, ks * 2 + bc_lo));
    };
    auto mma_block = [&](int buf) {
#pragma unroll
        for (int mi = 0; mi < 4; mi++)
#pragma unroll
            for (int nj = 0; nj < 4; nj++) {
                MMA16816(acc[mi][nj * 2 + 0],
                         af[buf][mi][0], af[buf][mi][1], af[buf][mi][2], af[buf][mi][3],
                         bf[nj][0], bf[nj][1]);
                MMA16816(acc[mi][nj * 2 + 1],
                         af[buf][mi][0], af[buf][mi][1], af[buf][mi][2], af[buf][mi][3],
                         bf[nj][2], bf[nj][3]);
            }
    };

    // prologue: stages 0 and 1 in flight; preload A fragments for (kt=0, ks=0)
    load_stage(0, 0);
    load_stage(1, 1);
    CP_WAIT1();                 // own-warp stage-0 loads retired
    __syncthreads();            // all warps' stage-0 loads retired
    ldsm_a(0, sbase, 0);

    for (int kt = 0; kt < NKT; kt++) {
        const int s = kt % NSTAGE;

        CP_WAIT0();             // stages <= kt+1 retired (own warp)
        __syncthreads();        // ... across all warps; prev-stage reads done

        const uint32_t a_s = sbase + s * STAGE_BYTES;
        const uint32_t b_s = a_s + A_BYTES;
        const uint32_t a_next = sbase + ((kt + 1) % NSTAGE) * STAGE_BYTES;

        // ks = 0: fragment LDSMs FIRST, then the 16-LDGSTS burst (its issue
        // time covers the LDSM latency), then the MMAs.
        ldsm_b(b_s, 0);
        ldsm_a(1, a_s, 1);
        if (kt + 2 < NKT) load_stage((kt + 2) % NSTAGE, kt + 2);
        mma_block(0);

        // ks = 1..3: as in R13 (A-fragment double buffer, cross-boundary
        // prefetch at ks=3 from stage kt+1, resident per wait0 above)
#pragma unroll
        for (int ks = 1; ks < 4; ks++) {
            ldsm_b(b_s, ks);
            if (ks < 3) ldsm_a((ks + 1) & 1, a_s, ks + 1);
            else        ldsm_a(0, a_next, 0);
            mma_block(ks & 1);
        }
    }

    // epilogue: out = acc * x_scale[row] + bias[col]  (streaming stores)
#pragma unroll
    for (int mi = 0; mi < 4; mi++) {
        const int row0 = bm + warp_m * 64 + mi * 16 + (lane >> 2);
        const int row1 = row0 + 8;
        const float xs0 = g_xscale[row0];
        const float xs1 = g_xscale[row1];
        float* p0 = out + (size_t)row0 * O_DIM + bn;
        float* p1 = out + (size_t)row1 * O_DIM + bn;
#pragma unroll
        for (int nj = 0; nj < 8; nj++) {
            const int col = warp_n * 64 + nj * 8 + (lane & 3) * 2;
            const float2 bv = *(const float2*)(bias + bn + col);
            float2 o0, o1;
            o0.x = acc[mi][nj][0] * xs0 + bv.x;
            o0.y = acc[mi][nj][1] * xs0 + bv.y;
            o1.x = acc[mi][nj][2] * xs1 + bv.x;
            o1.y = acc[mi][nj][3] * xs1 + bv.y;
            __stcs((float2*)(p0 + col), o0);
            __stcs((float2*)(p1 + col), o1);
        }
    }
}

// ---------------------------------------------------------------------------
extern "C" void kernel_launch(void* const* d_in, const int* in_sizes, int n_in,
                              void* d_out, int out_size) {
    const float* x        = (const float*)d_in[0];
    const int*   qweight  = (const int*)d_in[1];
    const float* w_scales = (const float*)d_in[2];
    const int*   w_zp     = (const int*)d_in[3];
    const float* bias     = (const float*)d_in[4];
    float*       out      = (float*)d_out;

    prep_kernel<<<S_TOK + O_DIM, 256>>>(x, qweight, w_scales, w_zp);

    cudaFuncSetAttribute(gemm_f16_kernel,
                         cudaFuncAttributeMaxDynamicSharedMemorySize, GEMM_SMEM);
    const int grid = (S_TOK / BM) * (O_DIM / BN);   // 16 x 32 = 512
    gemm_f16_kernel<<<grid, THREADS, GEMM_SMEM>>>(bias, out);
}